// round 14
// baseline (speedup 1.0000x reference)
#include <cuda_runtime.h>

#define NQ    12
#define DIM   4096
#define NL    4
#define NT    256
#define KPT   16
#define SWA(i) ((i) ^ ((((i) >> 4) & 7) << 1))
#define SWB(i) ((i) ^ (((i) >> 4) & 0xF))

struct cplx { float x, y; };

__device__ __forceinline__ cplx cmul(cplx a, cplx b) {
    return { a.x*b.x - a.y*b.y, a.x*b.y + a.y*b.x };
}
__device__ __forceinline__ cplx cadd(cplx a, cplx b) {
    return { a.x + b.x, a.y + b.y };
}
__device__ __forceinline__ void mmul(const cplx* A, const cplx* B, cplx* C) {
    C[0] = cadd(cmul(A[0], B[0]), cmul(A[1], B[2]));
    C[1] = cadd(cmul(A[0], B[1]), cmul(A[1], B[3]));
    C[2] = cadd(cmul(A[2], B[0]), cmul(A[3], B[2]));
    C[3] = cadd(cmul(A[2], B[1]), cmul(A[3], B[3]));
}
__device__ __forceinline__ cplx eph(float2 e, int bit) {
    return { e.x, bit ? -e.y : e.y };
}

// Scaled fast-Givens butterfly on local register bit m of v[16].
__device__ __forceinline__ void apply_fast(float2* v, float w, int vb, int m) {
    if (!vb) {
        #pragma unroll
        for (int h = 0; h < 8; h++) {
            const int k0 = ((h >> m) << (m + 1)) | (h & ((1 << m) - 1));
            const int k1 = k0 | (1 << m);
            const float2 s0 = v[k0];
            const float2 s1 = v[k1];
            v[k0].x = fmaf(-w, s1.x, s0.x);
            v[k0].y = fmaf(-w, s1.y, s0.y);
            v[k1].x = fmaf( w, s0.x, s1.x);
            v[k1].y = fmaf( w, s0.y, s1.y);
        }
    } else {
        #pragma unroll
        for (int h = 0; h < 8; h++) {
            const int k0 = ((h >> m) << (m + 1)) | (h & ((1 << m) - 1));
            const int k1 = k0 | (1 << m);
            const float2 s0 = v[k0];
            const float2 s1 = v[k1];
            v[k0].x = fmaf(w, s0.x, -s1.x);
            v[k0].y = fmaf(w, s0.y, -s1.y);
            v[k1].x = fmaf(w, s1.x, s0.x);
            v[k1].y = fmaf(w, s1.y, s0.y);
        }
    }
}

extern __shared__ float2 dsm[];   // elem e: A = dsm + e*2*DIM, B = A + DIM

__global__ __launch_bounds__(NT, 1)
void qsim_kernel(const float* __restrict__ x,
                 const float* __restrict__ params,
                 float* __restrict__ out)
{
    __shared__ float2 RYcs[2][NL][NQ];
    __shared__ float  FC[2][NL][NQ];
    __shared__ int    VF[2][NL][NQ];
    __shared__ float  SCL[2][NL][NQ];
    __shared__ float2 EG[2][NL][NQ], EA[2][NL][NQ];
    __shared__ float2 TA2[2][NL-1][2][16];
    __shared__ float2 TBt[2][NL-1][32];
    __shared__ float2 TCt[2][NL-1][16];
    __shared__ float2 E3[2][2][8];
    __shared__ float  Ssq[2];
    __shared__ float  red[2][NT / 32];

    const int t  = threadIdx.x;
    const int b0 = blockIdx.x * 2;

    float2* __restrict__ Ast0 = dsm;
    float2* __restrict__ Bst0 = dsm + DIM;
    float2* __restrict__ Ast1 = dsm + 2 * DIM;
    float2* __restrict__ Bst1 = dsm + 3 * DIM;

    // ---- phase 1: 96 fused gates (2 elements x 48) + ZYZ ----
    if (t < 96) {
        const int e = t / 48;
        const int r = t % 48;
        const int l = r / NQ;
        const int q = r % NQ;
        const float xv = x[b0 + e];
        const float x1 = asinf(xv);
        const float x2 = acosf(xv * xv);

        float c, s;
        sincosf(0.5f * x1, &s, &c);
        cplx RY[4]  = { {c,0.f}, {-s,0.f}, {s,0.f}, {c,0.f} };
        sincosf(0.5f * x2, &s, &c);
        cplx RZ[4]  = { {c,-s}, {0.f,0.f}, {0.f,0.f}, {c,s} };

        const float t0 = params[q * (NL * 3) + l * 3 + 0];
        const float t1 = params[q * (NL * 3) + l * 3 + 1];
        const float t2 = params[q * (NL * 3) + l * 3 + 2];

        sincosf(0.5f * t0, &s, &c);
        cplx RX0[4] = { {c,0.f}, {0.f,-s}, {0.f,-s}, {c,0.f} };
        sincosf(0.5f * t1, &s, &c);
        cplx RZ1[4] = { {c,-s}, {0.f,0.f}, {0.f,0.f}, {c,s} };
        sincosf(0.5f * t2, &s, &c);
        cplx RX2[4] = { {c,0.f}, {0.f,-s}, {0.f,-s}, {c,0.f} };

        cplx A[4], B[4];
        mmul(RZ,  RY, A);
        mmul(RX0, A,  B);
        mmul(RZ1, B,  A);
        mmul(RX2, A,  B);

        const float cc = sqrtf(B[0].x*B[0].x + B[0].y*B[0].y);
        const float ss = sqrtf(B[2].x*B[2].x + B[2].y*B[2].y);
        RYcs[e][l][q] = make_float2(cc, ss);
        if (cc >= ss) { FC[e][l][q] = ss / cc; VF[e][l][q] = 0; SCL[e][l][q] = cc; }
        else          { FC[e][l][q] = cc / ss; VF[e][l][q] = 1; SCL[e][l][q] = ss; }

        const float aa = atan2f(-B[0].y, B[0].x);
        const float bb = atan2f( B[2].y, B[2].x);
        float sg, cg, sa, ca;
        sincosf(0.5f * (aa - bb), &sg, &cg);
        sincosf(0.5f * (aa + bb), &sa, &ca);
        EG[e][l][q] = make_float2(cg, -sg);
        EA[e][l][q] = make_float2(ca, -sa);
    }
    __syncthreads();

    // ---- phase 2 (boundary diagonal tables, 480 entries) overlapped with layer 0 ----
    #pragma unroll
    for (int it = 0; it < 2; it++) {
        const int idx = t + it * NT;
        if (idx < 480) {
            const int e  = idx / 240;
            const int rr = idx % 240;
            const int bd = rr / 80;
            const int r  = rr % 80;
            cplx d = {1.f, 0.f};
            if (r < 32) {
                const int c7 = r >> 4;
                const int k  = r & 15;
                const int k3 = (k >> 3) & 1, k2 = (k >> 2) & 1, k1 = (k >> 1) & 1, k0 = k & 1;
                d = cmul(d, eph(EG[e][bd+1][0], k3));  d = cmul(d, eph(EA[e][bd][0], k3));
                d = cmul(d, eph(EG[e][bd+1][1], k2));  d = cmul(d, eph(EA[e][bd][1], k2 ^ k3));
                d = cmul(d, eph(EG[e][bd+1][2], k1));  d = cmul(d, eph(EA[e][bd][2], k1 ^ k2));
                d = cmul(d, eph(EG[e][bd+1][3], k0));  d = cmul(d, eph(EA[e][bd][3], k0 ^ k1));
                d = cmul(d, eph(EG[e][bd+1][4], c7));  d = cmul(d, eph(EA[e][bd][4], c7 ^ k0));
                TA2[e][bd][c7][k] = make_float2(d.x, d.y);
            } else if (r < 64) {
                const int u = r - 32;
                const int u4 = (u >> 4) & 1, u3 = (u >> 3) & 1, u2 = (u >> 2) & 1,
                          u1 = (u >> 1) & 1, u0 = u & 1;
                d = cmul(d, eph(EG[e][bd+1][5], u3));  d = cmul(d, eph(EA[e][bd][5], u3 ^ u4));
                d = cmul(d, eph(EG[e][bd+1][6], u2));  d = cmul(d, eph(EA[e][bd][6], u2 ^ u3));
                d = cmul(d, eph(EG[e][bd+1][7], u1));  d = cmul(d, eph(EA[e][bd][7], u1 ^ u2));
                d = cmul(d, eph(EG[e][bd+1][8], u0));  d = cmul(d, eph(EA[e][bd][8], u0 ^ u1));
                TBt[e][bd][u] = make_float2(d.x, d.y);
            } else {
                const int w = r - 64;
                const int w3 = (w >> 3) & 1, w2 = (w >> 2) & 1, w1 = (w >> 1) & 1, w0 = w & 1;
                d = cmul(d, eph(EG[e][bd+1][9],  w2)); d = cmul(d, eph(EA[e][bd][9],  w2 ^ w3));
                d = cmul(d, eph(EG[e][bd+1][10], w1)); d = cmul(d, eph(EA[e][bd][10], w1 ^ w2));
                d = cmul(d, eph(EG[e][bd+1][11], w0)); d = cmul(d, eph(EA[e][bd][11], w0 ^ w1));
                TCt[e][bd][w] = make_float2(d.x, d.y);
            }
        }
    }

    // ---- layer 0: real Kronecker columns (both elements, overlapped with phase 2) ----
    #pragma unroll
    for (int e = 0; e < 2; e++) {
        float2* __restrict__ Ast = e ? Ast1 : Ast0;
        float w = 1.f;
        #pragma unroll
        for (int q = 0; q < 8; q++) {
            const float2 cs = RYcs[e][0][q];
            w *= ((t >> (7 - q)) & 1) ? cs.y : cs.x;
        }
        const float2 c8 = RYcs[e][0][8],  c9  = RYcs[e][0][9];
        const float2 c10 = RYcs[e][0][10], c11 = RYcs[e][0][11];
        const int base = t << 4;
        #pragma unroll
        for (int j = 0; j < 8; j++) {
            const int k0 = 2 * j, k1 = 2 * j + 1;
            const float col0 = ((k0 & 8) ? c8.y : c8.x) * ((k0 & 4) ? c9.y : c9.x) *
                               ((k0 & 2) ? c10.y : c10.x) * ((k0 & 1) ? c11.y : c11.x);
            const float col1 = ((k1 & 8) ? c8.y : c8.x) * ((k1 & 4) ? c9.y : c9.x) *
                               ((k1 & 2) ? c10.y : c10.x) * ((k1 & 1) ? c11.y : c11.x);
            *(float4*)&Ast[SWA(base | k0)] = make_float4(w * col0, 0.f, w * col1, 0.f);
        }
    }
    __syncthreads();

    float2 v0[KPT], v1[KPT];

    // dual-element fast-Givens pass
    #define FAST_PASS2(L, P)                                                  \
        {                                                                     \
            _Pragma("unroll")                                                 \
            for (int m = 0; m < 4; m++) {                                     \
                const int q = 4*(P) + 3 - m;                                  \
                apply_fast(v0, FC[0][L][q], VF[0][L][q], m);                  \
                apply_fast(v1, FC[1][L][q], VF[1][L][q], m);                  \
            }                                                                 \
        }

    // ======== layers 1..2 ========
    for (int l = 1; l <= 2; l++) {
        const int bd = l - 1;

        // pass 0: perm-gather + boundary diag (both elements), store -> B buffers
        {
            #pragma unroll
            for (int e = 0; e < 2; e++) {
                float2* __restrict__ Ast = e ? Ast1 : Ast0;
                float2* vv = e ? v1 : v0;
                const float2 tb = TBt[e][bd][(t >> 3) & 31];
                const float2 tc = TCt[e][bd][t & 15];
                const cplx  sc = cmul(cplx{tb.x, tb.y}, cplx{tc.x, tc.y});
                const float2* ta = &TA2[e][bd][(t >> 7) & 1][0];
                #pragma unroll
                for (int k = 0; k < KPT; k++) {
                    const int i = (k << 8) | t;
                    const int j = i ^ (i >> 1);
                    const float2 s0 = Ast[SWA(j)];
                    const float2 a  = ta[k];
                    const cplx  d  = cmul(sc, cplx{a.x, a.y});
                    vv[k].x = d.x*s0.x - d.y*s0.y;
                    vv[k].y = d.x*s0.y + d.y*s0.x;
                }
            }
            if (l == 1) {
                // piggyback: layer-3 relative phases + global scales (TA2 synced)
                if (t < 32) {
                    const int e  = t / 16;
                    const int c7 = (t >> 3) & 1;
                    const int k  = t & 7;
                    const float2 d1 = TA2[e][2][c7][k | 8];
                    const float2 d0 = TA2[e][2][c7][k];
                    E3[e][c7][k] = make_float2(d1.x*d0.x + d1.y*d0.y,
                                               d1.y*d0.x - d1.x*d0.y);
                }
                if (t >= 254) {
                    const int e = t - 254;
                    float S = 1.f;
                    #pragma unroll
                    for (int ll = 1; ll <= 2; ll++)
                        #pragma unroll
                        for (int q = 0; q < NQ; q++) S *= SCL[e][ll][q];
                    Ssq[e] = S * S;
                }
            }
            FAST_PASS2(l, 0)
            #pragma unroll
            for (int k = 0; k < KPT; k++) {
                Bst0[SWB((k << 8) | t)] = v0[k];
                Bst1[SWB((k << 8) | t)] = v1[k];
            }
            __syncthreads();
        }

        // pass 1 (bits 7..4): gather B, store -> A
        {
            const int base = ((t & 0xF0) << 4) | (t & 0x0F);
            #pragma unroll
            for (int k = 0; k < KPT; k++) {
                v0[k] = Bst0[SWB(base | (k << 4))];
                v1[k] = Bst1[SWB(base | (k << 4))];
            }
            FAST_PASS2(l, 1)
            #pragma unroll
            for (int k = 0; k < KPT; k++) {
                Ast0[SWA(base | (k << 4))] = v0[k];
                Ast1[SWA(base | (k << 4))] = v1[k];
            }
            __syncthreads();
        }

        // pass 2 (bits 3..0): in-place on A, float4
        {
            const int base = t << 4;
            #pragma unroll
            for (int j = 0; j < 8; j++) {
                const float4 w0 = *(const float4*)&Ast0[SWA(base | (2 * j))];
                const float4 w1 = *(const float4*)&Ast1[SWA(base | (2 * j))];
                v0[2*j]   = make_float2(w0.x, w0.y);
                v0[2*j+1] = make_float2(w0.z, w0.w);
                v1[2*j]   = make_float2(w1.x, w1.y);
                v1[2*j+1] = make_float2(w1.z, w1.w);
            }
            FAST_PASS2(l, 2)
            #pragma unroll
            for (int j = 0; j < 8; j++) {
                *(float4*)&Ast0[SWA(base | (2 * j))] =
                    make_float4(v0[2*j].x, v0[2*j].y, v0[2*j+1].x, v0[2*j+1].y);
                *(float4*)&Ast1[SWA(base | (2 * j))] =
                    make_float4(v1[2*j].x, v1[2*j].y, v1[2*j+1].x, v1[2*j+1].y);
            }
            __syncthreads();
        }
    }

    // ======== layer 3 collapsed (both elements) ========
    float acc0 = 0.f, acc1 = 0.f;
    {
        const float2 csA = RYcs[0][3][0];
        const float2 csB = RYcs[1][3][0];
        const float2* e3A = &E3[0][(t >> 7) & 1][0];
        const float2* e3B = &E3[1][(t >> 7) & 1][0];
        #pragma unroll
        for (int k = 0; k < 8; k++) {
            const int i0 = (k << 8) | t;
            const int i1 = ((k | 8) << 8) | t;
            const int j0 = SWA(i0 ^ (i0 >> 1));
            const int j1 = SWA(i1 ^ (i1 >> 1));
            {
                const float2 s0 = Ast0[j0];
                const float2 s1 = Ast0[j1];
                const float2 e  = e3A[k];
                const float ex = e.x*s1.x - e.y*s1.y;
                const float ey = e.x*s1.y + e.y*s1.x;
                const float r0x = csA.x*s0.x - csA.y*ex;
                const float r0y = csA.x*s0.y - csA.y*ey;
                const float r1x = csA.y*s0.x + csA.x*ex;
                const float r1y = csA.y*s0.y + csA.x*ey;
                acc0 += (r0x*r0x + r0y*r0y) - (r1x*r1x + r1y*r1y);
            }
            {
                const float2 s0 = Ast1[j0];
                const float2 s1 = Ast1[j1];
                const float2 e  = e3B[k];
                const float ex = e.x*s1.x - e.y*s1.y;
                const float ey = e.x*s1.y + e.y*s1.x;
                const float r0x = csB.x*s0.x - csB.y*ex;
                const float r0y = csB.x*s0.y - csB.y*ey;
                const float r1x = csB.y*s0.x + csB.x*ex;
                const float r1y = csB.y*s0.y + csB.x*ey;
                acc1 += (r0x*r0x + r0y*r0y) - (r1x*r1x + r1y*r1y);
            }
        }
    }

    #pragma unroll
    for (int o = 16; o > 0; o >>= 1) {
        acc0 += __shfl_xor_sync(0xffffffffu, acc0, o);
        acc1 += __shfl_xor_sync(0xffffffffu, acc1, o);
    }
    if ((t & 31) == 0) { red[0][t >> 5] = acc0; red[1][t >> 5] = acc1; }
    __syncthreads();
    if (t < 32) {
        float r0 = (t < NT / 32) ? red[0][t] : 0.f;
        float r1 = (t < NT / 32) ? red[1][t] : 0.f;
        #pragma unroll
        for (int o = 4; o > 0; o >>= 1) {
            r0 += __shfl_xor_sync(0xffffffffu, r0, o);
            r1 += __shfl_xor_sync(0xffffffffu, r1, o);
        }
        if (t == 0) {
            out[b0]     = r0 * Ssq[0];
            out[b0 + 1] = r1 * Ssq[1];
        }
    }
}

extern "C" void kernel_launch(void* const* d_in, const int* in_sizes, int n_in,
                              void* d_out, int out_size)
{
    const float* x      = (const float*)d_in[0];
    const float* params = (const float*)d_in[1];
    if (n_in >= 2 && in_sizes[0] != 256 && in_sizes[1] == 256) {
        x      = (const float*)d_in[1];
        params = (const float*)d_in[0];
    }
    float* out = (float*)d_out;

    const size_t smem = (size_t)(4 * DIM) * sizeof(float2);   // 128 KB dynamic
    static bool attr_set = false;
    if (!attr_set) {
        cudaFuncSetAttribute(qsim_kernel, cudaFuncAttributeMaxDynamicSharedMemorySize,
                             (int)smem);
        attr_set = true;
    }
    qsim_kernel<<<128, NT, smem>>>(x, params, out);
}

// round 16
// speedup vs baseline: 1.1397x; 1.1397x over previous
#include <cuda_runtime.h>

#define NQ    12
#define DIM   4096
#define NL    4
#define NT    256
#define KPT   16

// swizzle XOR map: s = (i>>4)&7 -> bits (1,2,3) = (s0^s1^s2, s1^s2, s0^s1)
__host__ __device__ constexpr int SWXb(int s) {
    return ((((s ^ (s >> 1) ^ (s >> 2)) & 1) << 1) |
            ((((s >> 1) ^ (s >> 2)) & 1) << 2) |
            (((s ^ (s >> 1)) & 1) << 3));
}
__host__ __device__ constexpr int G4v(int k) { return (k ^ (k >> 1)) & 15; }
__host__ __device__ constexpr int MKf(int k) { return (k << 4) ^ SWXb(k & 7); }

struct cplx { float x, y; };

__device__ __forceinline__ cplx cmul(cplx a, cplx b) {
    return { a.x*b.x - a.y*b.y, a.x*b.y + a.y*b.x };
}
__device__ __forceinline__ cplx cadd(cplx a, cplx b) {
    return { a.x + b.x, a.y + b.y };
}
__device__ __forceinline__ void mmul(const cplx* A, const cplx* B, cplx* C) {
    C[0] = cadd(cmul(A[0], B[0]), cmul(A[1], B[2]));
    C[1] = cadd(cmul(A[0], B[1]), cmul(A[1], B[3]));
    C[2] = cadd(cmul(A[2], B[0]), cmul(A[3], B[2]));
    C[3] = cadd(cmul(A[2], B[1]), cmul(A[3], B[3]));
}
__device__ __forceinline__ cplx eph(float2 e, int bit) {
    return { e.x, bit ? -e.y : e.y };
}

// Scaled fast-Givens butterfly on local register bit m of v[16].
__device__ __forceinline__ void apply_fast(float2* v, float w, int vb, int m) {
    if (!vb) {
        #pragma unroll
        for (int h = 0; h < 8; h++) {
            const int k0 = ((h >> m) << (m + 1)) | (h & ((1 << m) - 1));
            const int k1 = k0 | (1 << m);
            const float2 s0 = v[k0];
            const float2 s1 = v[k1];
            v[k0].x = fmaf(-w, s1.x, s0.x);
            v[k0].y = fmaf(-w, s1.y, s0.y);
            v[k1].x = fmaf( w, s0.x, s1.x);
            v[k1].y = fmaf( w, s0.y, s1.y);
        }
    } else {
        #pragma unroll
        for (int h = 0; h < 8; h++) {
            const int k0 = ((h >> m) << (m + 1)) | (h & ((1 << m) - 1));
            const int k1 = k0 | (1 << m);
            const float2 s0 = v[k0];
            const float2 s1 = v[k1];
            v[k0].x = fmaf(w, s0.x, -s1.x);
            v[k0].y = fmaf(w, s0.y, -s1.y);
            v[k1].x = fmaf(w, s1.x, s0.x);
            v[k1].y = fmaf(w, s1.y, s0.y);
        }
    }
}

extern __shared__ float2 dsm[];   // [0,DIM): buffer A, [DIM,2*DIM): buffer B

__global__ __launch_bounds__(NT, 2)
void qsim_kernel(const float* __restrict__ x,
                 const float* __restrict__ params,
                 float* __restrict__ out)
{
    float2* __restrict__ Ast = dsm;
    float2* __restrict__ Bst = dsm + DIM;

    __shared__ float2 RYcs[NL][NQ];
    __shared__ float  FC[NL][NQ];
    __shared__ int    VF[NL][NQ];
    __shared__ float  SCL[NL][NQ];
    __shared__ float2 EG[NL][NQ], EA[NL][NQ];
    __shared__ float2 TA[2][16];        // boundary diag: i bits 11..8 (q0..3)
    __shared__ float2 TB2[2][2][16];    // [bd][i8][i7..4]   (q4..7)
    __shared__ float2 TC2[2][2][16];    // [bd][i4][i3..0]   (q8..11)
    __shared__ float2 E3[2];            // layer-3 relative phase, indexed by i10
    __shared__ float  Ssq;
    __shared__ float  red[NT / 32];

    const int t = threadIdx.x;
    const int b = blockIdx.x;

    // ---- phase 1: 48 fused gates + ZYZ + fast-Givens decomposition ----
    if (t < NL * NQ) {
        const int l = t / NQ;
        const int q = t % NQ;
        const float xv = x[b];
        const float x1 = asinf(xv);
        const float x2 = acosf(xv * xv);

        float c, s;
        sincosf(0.5f * x1, &s, &c);
        cplx RY[4]  = { {c,0.f}, {-s,0.f}, {s,0.f}, {c,0.f} };
        sincosf(0.5f * x2, &s, &c);
        cplx RZ[4]  = { {c,-s}, {0.f,0.f}, {0.f,0.f}, {c,s} };

        const float t0 = params[q * (NL * 3) + l * 3 + 0];
        const float t1 = params[q * (NL * 3) + l * 3 + 1];
        const float t2 = params[q * (NL * 3) + l * 3 + 2];

        sincosf(0.5f * t0, &s, &c);
        cplx RX0[4] = { {c,0.f}, {0.f,-s}, {0.f,-s}, {c,0.f} };
        sincosf(0.5f * t1, &s, &c);
        cplx RZ1[4] = { {c,-s}, {0.f,0.f}, {0.f,0.f}, {c,s} };
        sincosf(0.5f * t2, &s, &c);
        cplx RX2[4] = { {c,0.f}, {0.f,-s}, {0.f,-s}, {c,0.f} };

        cplx A[4], B[4];
        mmul(RZ,  RY, A);
        mmul(RX0, A,  B);
        mmul(RZ1, B,  A);
        mmul(RX2, A,  B);   // fused U in SU(2)

        const float cc = sqrtf(B[0].x*B[0].x + B[0].y*B[0].y);
        const float ss = sqrtf(B[2].x*B[2].x + B[2].y*B[2].y);
        RYcs[l][q] = make_float2(cc, ss);
        if (cc >= ss) { FC[l][q] = ss / cc; VF[l][q] = 0; SCL[l][q] = cc; }
        else          { FC[l][q] = cc / ss; VF[l][q] = 1; SCL[l][q] = ss; }

        const float aa = atan2f(-B[0].y, B[0].x);
        const float bb = atan2f( B[2].y, B[2].x);
        float sg, cg, sa, ca;
        sincosf(0.5f * (aa - bb), &sg, &cg);
        sincosf(0.5f * (aa + bb), &sa, &ca);
        EG[l][q] = make_float2(cg, -sg);
        EA[l][q] = make_float2(ca, -sa);
    }
    __syncthreads();

    // ---- phase 2: boundary diag tables D(i) = gamma_{bd+1}(i) * alpha_bd(g(i)) ----
    // qubit q <-> bit 11-q; alpha bit for q: i_{11-q} ^ i_{12-q} (q=0: just i_11)
    if (t < 160) {
        const int bd = t / 80;
        const int r  = t % 80;
        cplx d = {1.f, 0.f};
        if (r < 16) {
            const int k = r;
            const int k3 = (k>>3)&1, k2 = (k>>2)&1, k1 = (k>>1)&1, k0 = k&1;
            d = cmul(d, eph(EG[bd+1][0], k3));  d = cmul(d, eph(EA[bd][0], k3));
            d = cmul(d, eph(EG[bd+1][1], k2));  d = cmul(d, eph(EA[bd][1], k2 ^ k3));
            d = cmul(d, eph(EG[bd+1][2], k1));  d = cmul(d, eph(EA[bd][2], k1 ^ k2));
            d = cmul(d, eph(EG[bd+1][3], k0));  d = cmul(d, eph(EA[bd][3], k0 ^ k1));
            TA[bd][k] = make_float2(d.x, d.y);
        } else if (r < 48) {
            const int c8 = (r - 16) >> 4;
            const int u  = (r - 16) & 15;
            const int u3 = (u>>3)&1, u2 = (u>>2)&1, u1 = (u>>1)&1, u0 = u&1;
            d = cmul(d, eph(EG[bd+1][4], u3));  d = cmul(d, eph(EA[bd][4], u3 ^ c8));
            d = cmul(d, eph(EG[bd+1][5], u2));  d = cmul(d, eph(EA[bd][5], u2 ^ u3));
            d = cmul(d, eph(EG[bd+1][6], u1));  d = cmul(d, eph(EA[bd][6], u1 ^ u2));
            d = cmul(d, eph(EG[bd+1][7], u0));  d = cmul(d, eph(EA[bd][7], u0 ^ u1));
            TB2[bd][c8][u] = make_float2(d.x, d.y);
        } else {
            const int c4 = (r - 48) >> 4;
            const int k  = (r - 48) & 15;
            const int k3 = (k>>3)&1, k2 = (k>>2)&1, k1 = (k>>1)&1, k0 = k&1;
            d = cmul(d, eph(EG[bd+1][8],  k3)); d = cmul(d, eph(EA[bd][8],  k3 ^ c4));
            d = cmul(d, eph(EG[bd+1][9],  k2)); d = cmul(d, eph(EA[bd][9],  k2 ^ k3));
            d = cmul(d, eph(EG[bd+1][10], k1)); d = cmul(d, eph(EA[bd][10], k1 ^ k2));
            d = cmul(d, eph(EG[bd+1][11], k0)); d = cmul(d, eph(EA[bd][11], k0 ^ k1));
            TC2[bd][c4][k] = make_float2(d.x, d.y);
        }
    }
    // layer-3 relative phase: flip of i11 hits q0 (gamma&alpha) and q1 (alpha @ i10^i11)
    if (t == 160) {
        const float2 g0 = EG[3][0], a0 = EA[2][0], a1 = EA[2][1];
        const cplx C = cmul(cplx{g0.x*g0.x - g0.y*g0.y, -2.f*g0.x*g0.y},
                            cplx{a0.x*a0.x - a0.y*a0.y, -2.f*a0.x*a0.y});
        const cplx e0 = cmul(C, cplx{a1.x*a1.x - a1.y*a1.y, -2.f*a1.x*a1.y});
        const cplx e1 = cmul(C, cplx{a1.x*a1.x - a1.y*a1.y,  2.f*a1.x*a1.y});
        E3[0] = make_float2(e0.x, e0.y);
        E3[1] = make_float2(e1.x, e1.y);
    }
    if (t == 161) {
        float S = 1.f;
        #pragma unroll
        for (int l = 1; l <= 2; l++)
            #pragma unroll
            for (int q = 0; q < NQ; q++) S *= SCL[l][q];
        Ssq = S * S;
    }

    // ---- per-thread loop-invariant swizzled bases ----
    const int H8   = (t ^ (t >> 1)) & 0xFF;            // perm high bits
    const int pb   = (t & 1) << 3;                      // perm bit-3 coupling
    const int BLg  = ((H8 << 4) ^ SWXb(H8 & 7)) ^ pb;   // L-pass perm-gather base
    const int BSb  = (t << 4) ^ SWXb(t & 7);            // block store/load base
    const int BMg  = ((t >> 4) << 8) | (t & 15);        // M-pass base (XOR MKf(k))
    const int BH   = t ^ SWXb((t >> 4) & 7);            // H-pass base (XOR k<<8)

    // ---- layer 0: real Kronecker column -> A (float4 block stores) ----
    {
        float w = 1.f;
        #pragma unroll
        for (int q = 0; q < 8; q++) {
            const float2 cs = RYcs[0][q];
            w *= ((t >> (7 - q)) & 1) ? cs.y : cs.x;
        }
        const float2 c8 = RYcs[0][8], c9 = RYcs[0][9], c10 = RYcs[0][10], c11 = RYcs[0][11];
        #pragma unroll
        for (int j = 0; j < 8; j++) {
            const int k0 = 2 * j, k1 = 2 * j + 1;
            const float col0 = ((k0 & 8) ? c8.y : c8.x) * ((k0 & 4) ? c9.y : c9.x) *
                               ((k0 & 2) ? c10.y : c10.x) * ((k0 & 1) ? c11.y : c11.x);
            const float col1 = ((k1 & 8) ? c8.y : c8.x) * ((k1 & 4) ? c9.y : c9.x) *
                               ((k1 & 2) ? c10.y : c10.x) * ((k1 & 1) ? c11.y : c11.x);
            *(float4*)&Ast[BSb ^ k0] = make_float4(w * col0, 0.f, w * col1, 0.f);
        }
        __syncthreads();
    }

    float2 v[KPT];

    #define FAST_PASS(L, P)                                                   \
        {                                                                     \
            _Pragma("unroll")                                                 \
            for (int m = 0; m < 4; m++) {                                     \
                const int q = 4*(P) + 3 - m;                                  \
                apply_fast(v, FC[L][q], VF[L][q], m);                         \
            }                                                                 \
        }

    // ======== layers 1..2: L (bits 3..0) -> M (bits 7..4) -> H (bits 11..8) ====
    #pragma unroll
    for (int l = 1; l <= 2; l++) {
        const int bd = l - 1;

        // --- L pass: perm-folded block gather from A + boundary diag, store -> B
        {
            const float2 ta = TA[bd][t >> 4];
            const float2 tb = TB2[bd][(t >> 4) & 1][t & 15];
            const cplx  sc = cmul(cplx{ta.x, ta.y}, cplx{tb.x, tb.y});
            // half 0: lv slots 0..7
            {
                float2 lvh[8];
                #pragma unroll
                for (int j2 = 0; j2 < 4; j2++) {
                    const float4 w4 = *(const float4*)&Ast[BLg ^ (2 * j2)];
                    lvh[2*j2]   = make_float2(w4.x, w4.y);
                    lvh[2*j2+1] = make_float2(w4.z, w4.w);
                }
                #pragma unroll
                for (int k = 0; k < 8; k++) {
                    const float2 tc = TC2[bd][t & 1][k];
                    const cplx  d  = cmul(sc, cplx{tc.x, tc.y});
                    const float2 s0 = lvh[G4v(k)];
                    v[k].x = d.x*s0.x - d.y*s0.y;
                    v[k].y = d.x*s0.y + d.y*s0.x;
                }
            }
            // half 1: lv slots 8..15
            {
                float2 lvh[8];
                #pragma unroll
                for (int j2 = 4; j2 < 8; j2++) {
                    const float4 w4 = *(const float4*)&Ast[BLg ^ (2 * j2)];
                    lvh[2*(j2-4)]   = make_float2(w4.x, w4.y);
                    lvh[2*(j2-4)+1] = make_float2(w4.z, w4.w);
                }
                #pragma unroll
                for (int k = 8; k < 16; k++) {
                    const float2 tc = TC2[bd][t & 1][k];
                    const cplx  d  = cmul(sc, cplx{tc.x, tc.y});
                    const float2 s0 = lvh[G4v(k) & 7];
                    v[k].x = d.x*s0.x - d.y*s0.y;
                    v[k].y = d.x*s0.y + d.y*s0.x;
                }
            }
            FAST_PASS(l, 2)     // qubits 11..8 on bits 3..0
            #pragma unroll
            for (int j2 = 0; j2 < 8; j2++)
                *(float4*)&Bst[BSb ^ (2 * j2)] =
                    make_float4(v[2*j2].x, v[2*j2].y, v[2*j2+1].x, v[2*j2+1].y);
        }

        // --- M pass: intra-half-warp exchange in B (syncwarp only)
        __syncwarp();
        #pragma unroll
        for (int k = 0; k < KPT; k++) v[k] = Bst[BMg ^ MKf(k)];
        __syncwarp();
        FAST_PASS(l, 1)         // qubits 7..4 on bits 3..0 of k
        #pragma unroll
        for (int k = 0; k < KPT; k++) Bst[BMg ^ MKf(k)] = v[k];
        __syncthreads();

        // --- H pass: hi-stride gather from B, store -> A
        #pragma unroll
        for (int k = 0; k < KPT; k++) v[k] = Bst[(k << 8) ^ BH];
        FAST_PASS(l, 0)         // qubits 3..0 on bits 3..0 of k
        #pragma unroll
        for (int k = 0; k < KPT; k++) Ast[(k << 8) ^ BH] = v[k];
        __syncthreads();
    }

    // ======== layer 3 collapsed: perm-fold + E3 + qubit-0 RY + |.|^2 ========
    float acc = 0.f;
    {
        const int u7    = (t ^ (t >> 1)) & 0x7F;
        const int ue0   = u7 | ((t >> 7) << 7);
        const int baseJ = ue0 ^ SWXb((u7 >> 4) & 7);
        const float2 cs = RYcs[3][0];
        #pragma unroll
        for (int k = 0; k < 8; k++) {
            const int a0 = (G4v(k) << 8) ^ baseJ ^ ((k & 1) << 7);
            const int a1 = ((G4v(k) ^ 12) << 8) ^ baseJ ^ ((k & 1) << 7);
            const float2 s0 = Ast[a0];                 // i11 = 0 class
            const float2 s1 = Ast[a1];                 // i11 = 1 class
            const float2 e  = E3[(k >> 2) & 1];
            const float ex = e.x*s1.x - e.y*s1.y;
            const float ey = e.x*s1.y + e.y*s1.x;
            const float r0x = cs.x*s0.x - cs.y*ex;
            const float r0y = cs.x*s0.y - cs.y*ey;
            const float r1x = cs.y*s0.x + cs.x*ex;
            const float r1y = cs.y*s0.y + cs.x*ey;
            acc += (r0x*r0x + r0y*r0y) - (r1x*r1x + r1y*r1y);
        }
    }

    #pragma unroll
    for (int o = 16; o > 0; o >>= 1) acc += __shfl_xor_sync(0xffffffffu, acc, o);
    if ((t & 31) == 0) red[t >> 5] = acc;
    __syncthreads();
    if (t < 32) {
        float v2 = (t < NT / 32) ? red[t] : 0.f;
        #pragma unroll
        for (int o = 4; o > 0; o >>= 1) v2 += __shfl_xor_sync(0xffffffffu, v2, o);
        if (t == 0) out[b] = v2 * Ssq;
    }
}

extern "C" void kernel_launch(void* const* d_in, const int* in_sizes, int n_in,
                              void* d_out, int out_size)
{
    const float* x      = (const float*)d_in[0];
    const float* params = (const float*)d_in[1];
    if (n_in >= 2 && in_sizes[0] != 256 && in_sizes[1] == 256) {
        x      = (const float*)d_in[1];
        params = (const float*)d_in[0];
    }
    float* out = (float*)d_out;

    const size_t smem = (size_t)(2 * DIM) * sizeof(float2);   // 64 KB dynamic
    static bool attr_set = false;
    if (!attr_set) {
        cudaFuncSetAttribute(qsim_kernel, cudaFuncAttributeMaxDynamicSharedMemorySize,
                             (int)smem);
        attr_set = true;
    }
    qsim_kernel<<<256, NT, smem>>>(x, params, out);
}